// round 2
// baseline (speedup 1.0000x reference)
#include <cuda_runtime.h>
#include <math.h>

#define NN 50000
#define EE 800000
#define FIN 128
#define HH 256
#define CC 112
#define LL 8
#define EPSBN 1e-5f

// ---------------- scratch (device globals; no allocation allowed) ------------
__device__ __align__(16) float g_h[NN * HH];
__device__ __align__(16) float g_t[NN * HH];
__device__ __align__(16) float g_acc[NN * HH];
__device__ __align__(16) float g_dinv1[NN];
__device__ __align__(16) float g_dinv2[NN];
__device__ __align__(16) float g_self1[NN];
__device__ __align__(16) float g_self2[NN];
__device__ __align__(16) float g_norm1[EE];
__device__ __align__(16) float g_norm2[EE];
__device__ __align__(16) float g_stats[2 * HH];   // [0:256) sum, [256:512) sumsq
__device__ __align__(16) float g_ab[2 * HH];      // [0:256) scale a, [256:512) shift b
__device__ __align__(16) float g_w[LL];

// ---------------- utility kernels -------------------------------------------
__global__ void zero_kernel(float4* p, int n4) {
    int i = blockIdx.x * blockDim.x + threadIdx.x;
    if (i < n4) p[i] = make_float4(0.f, 0.f, 0.f, 0.f);
}

// degrees of target (col) nodes for both adjacencies; +1 self loop added later
__global__ void deg_kernel(const int* __restrict__ e1, const int* __restrict__ e2) {
    int i = blockIdx.x * blockDim.x + threadIdx.x;
    if (i < EE) {
        atomicAdd(&g_dinv1[e1[EE + i]], 1.0f);
        atomicAdd(&g_dinv2[e2[EE + i]], 1.0f);
    }
}

__global__ void dinv_kernel() {
    int i = blockIdx.x * blockDim.x + threadIdx.x;
    if (i < NN) {
        float d1 = rsqrtf(g_dinv1[i] + 1.0f);   // +1 = self loop
        float d2 = rsqrtf(g_dinv2[i] + 1.0f);
        g_dinv1[i] = d1;
        g_dinv2[i] = d2;
        g_self1[i] = d1 * d1;
        g_self2[i] = d2 * d2;
    }
}

__global__ void norm_kernel(const int* __restrict__ e1, const int* __restrict__ e2) {
    int i = blockIdx.x * blockDim.x + threadIdx.x;
    if (i < EE) {
        g_norm1[i] = g_dinv1[e1[i]] * g_dinv1[e1[EE + i]];
        g_norm2[i] = g_dinv2[e2[i]] * g_dinv2[e2[EE + i]];
    }
}

__global__ void softmax_w_kernel(const float* __restrict__ lw) {
    if (threadIdx.x == 0 && blockIdx.x == 0) {
        float m = lw[0];
        for (int i = 1; i < LL; i++) m = fmaxf(m, lw[i]);
        float e[LL];
        float s = 0.f;
        for (int i = 0; i < LL; i++) { e[i] = expf(lw[i] - m); s += e[i]; }
        float inv = 1.0f / s;
        for (int i = 0; i < LL; i++) g_w[i] = e[i] * inv;
    }
}

// ---------------- SGEMM: C[M,N] = A[M,K] @ B[K,N] + bias[N] ------------------
// 128x128 tile, BK=16, 256 threads, 8x8 per thread.
__global__ __launch_bounds__(256) void sgemm_bias_kernel(
    const float* __restrict__ A, const float* __restrict__ B,
    const float* __restrict__ bias, float* __restrict__ C,
    int M, int Ncols, int K)
{
    __shared__ float As[16][128];
    __shared__ float Bs[16][128];
    const int tid = threadIdx.x;
    const int tx = tid & 15;
    const int ty = tid >> 4;
    const int rowBase = blockIdx.y * 128;
    const int colBase = blockIdx.x * 128;
    const int aRow = tid >> 2;          // 0..63
    const int aCol = (tid & 3) * 4;     // 0,4,8,12
    const int bRow = tid >> 5;          // 0..7
    const int bCol = (tid & 31) * 4;    // 0..124

    float acc[8][8];
#pragma unroll
    for (int i = 0; i < 8; i++)
#pragma unroll
        for (int j = 0; j < 8; j++) acc[i][j] = 0.f;

    for (int k0 = 0; k0 < K; k0 += 16) {
#pragma unroll
        for (int s = 0; s < 2; s++) {
            int r = aRow + s * 64;
            int gr = rowBase + r;
            float4 v = make_float4(0.f, 0.f, 0.f, 0.f);
            if (gr < M) v = *(const float4*)(A + (long)gr * K + k0 + aCol);
            As[aCol + 0][r] = v.x;
            As[aCol + 1][r] = v.y;
            As[aCol + 2][r] = v.z;
            As[aCol + 3][r] = v.w;
        }
#pragma unroll
        for (int s = 0; s < 2; s++) {
            int r = bRow + s * 8;
            int gc = colBase + bCol;
            float4 v = make_float4(0.f, 0.f, 0.f, 0.f);
            if (gc + 3 < Ncols) {
                v = *(const float4*)(B + (long)(k0 + r) * Ncols + gc);
            } else {
                float tmp[4] = {0.f, 0.f, 0.f, 0.f};
                for (int j = 0; j < 4; j++)
                    if (gc + j < Ncols) tmp[j] = B[(long)(k0 + r) * Ncols + gc + j];
                v = make_float4(tmp[0], tmp[1], tmp[2], tmp[3]);
            }
            *(float4*)(&Bs[r][bCol]) = v;
        }
        __syncthreads();
#pragma unroll
        for (int kk = 0; kk < 16; kk++) {
            float ar[8], br[8];
#pragma unroll
            for (int i = 0; i < 8; i++) ar[i] = As[kk][ty * 8 + i];
#pragma unroll
            for (int j = 0; j < 8; j++) br[j] = Bs[kk][tx * 8 + j];
#pragma unroll
            for (int i = 0; i < 8; i++)
#pragma unroll
                for (int j = 0; j < 8; j++)
                    acc[i][j] = fmaf(ar[i], br[j], acc[i][j]);
        }
        __syncthreads();
    }

#pragma unroll
    for (int i = 0; i < 8; i++) {
        int gr = rowBase + ty * 8 + i;
        if (gr >= M) continue;
#pragma unroll
        for (int j = 0; j < 8; j += 4) {
            int gc = colBase + tx * 8 + j;
            if (gc + 3 < Ncols) {
                float4 bv = *(const float4*)(bias + gc);
                float4 o;
                o.x = acc[i][j + 0] + bv.x;
                o.y = acc[i][j + 1] + bv.y;
                o.z = acc[i][j + 2] + bv.z;
                o.w = acc[i][j + 3] + bv.w;
                *(float4*)(C + (long)gr * Ncols + gc) = o;
            } else {
                for (int j2 = 0; j2 < 4; j2++)
                    if (gc + j2 < Ncols)
                        C[(long)gr * Ncols + gc + j2] = acc[i][j + j2] + bias[gc + j2];
            }
        }
    }
}

// ---------------- scatter-add SpMM (one warp per edge) -----------------------
__global__ __launch_bounds__(256) void scatter_kernel(
    const float* __restrict__ t, const int* __restrict__ edge,
    const float* __restrict__ norm)
{
    int e = blockIdx.x * 8 + (threadIdx.x >> 5);
    if (e >= EE) return;
    int lane = threadIdx.x & 31;
    int r = edge[e];          // source
    int c = edge[EE + e];     // target
    float nv = norm[e];
    const float4* src = (const float4*)(t + (long)r * HH);
    float* dst = g_h + (long)c * HH;
#pragma unroll
    for (int p = 0; p < 2; p++) {
        float4 v = src[lane + 32 * p];
        float* d = dst + (lane + 32 * p) * 4;
        asm volatile("red.global.add.v4.f32 [%0], {%1,%2,%3,%4};"
                     :: "l"(d), "f"(v.x * nv), "f"(v.y * nv),
                        "f"(v.z * nv), "f"(v.w * nv)
                     : "memory");
    }
}

// self-loop contribution: h[n,:] += t[n,:] * selfnorm[n]   (exclusive, no atomics)
__global__ void self_add_kernel(const float* __restrict__ t,
                                const float* __restrict__ selfn) {
    int idx = blockIdx.x * blockDim.x + threadIdx.x;   // float4 index
    if (idx < NN * (HH / 4)) {
        int n = idx >> 6;
        float s = selfn[n];
        float4 v = ((const float4*)t)[idx];
        float4 h = ((float4*)g_h)[idx];
        h.x += v.x * s; h.y += v.y * s; h.z += v.z * s; h.w += v.w * s;
        ((float4*)g_h)[idx] = h;
    }
}

// per-feature sum / sumsq partials
__global__ void stats_kernel() {
    int f = threadIdx.x;                 // 256 features
    int r0 = blockIdx.x * 256;
    int rend = min(r0 + 256, NN);
    float s = 0.f, q = 0.f;
    for (int r = r0; r < rend; r++) {
        float v = g_h[(long)r * HH + f];
        s += v;
        q = fmaf(v, v, q);
    }
    atomicAdd(&g_stats[f], s);
    atomicAdd(&g_stats[HH + f], q);
}

__global__ void bn_finalize_kernel(const float* __restrict__ gamma,
                                   const float* __restrict__ beta, int layer) {
    int f = threadIdx.x;
    float mu = g_stats[f] * (1.0f / NN);
    float var = g_stats[HH + f] * (1.0f / NN) - mu * mu;
    float rs = rsqrtf(var + EPSBN);
    float a = rs * gamma[layer * HH + f];
    float b = beta[layer * HH + f] - mu * a;
    g_ab[f] = a;
    g_ab[HH + f] = b;
}

__global__ void bn_relu_acc_kernel(int layer) {
    int idx = blockIdx.x * blockDim.x + threadIdx.x;   // float4 index
    if (idx < NN * (HH / 4)) {
        int f4 = (idx & 63) * 4;
        float4 a = *(const float4*)(g_ab + f4);
        float4 b = *(const float4*)(g_ab + HH + f4);
        float4 v = ((float4*)g_h)[idx];
        v.x = fmaxf(fmaf(v.x, a.x, b.x), 0.f);
        v.y = fmaxf(fmaf(v.y, a.y, b.y), 0.f);
        v.z = fmaxf(fmaf(v.z, a.z, b.z), 0.f);
        v.w = fmaxf(fmaf(v.w, a.w, b.w), 0.f);
        ((float4*)g_h)[idx] = v;
        float w = g_w[layer];
        float4 ac = ((float4*)g_acc)[idx];
        ac.x = fmaf(w, v.x, ac.x);
        ac.y = fmaf(w, v.y, ac.y);
        ac.z = fmaf(w, v.z, ac.z);
        ac.w = fmaf(w, v.w, ac.w);
        ((float4*)g_acc)[idx] = ac;
    }
}

// fused out FC + log-softmax: one block per node row
__global__ __launch_bounds__(128) void out_kernel(
    const float* __restrict__ outW, const float* __restrict__ outb,
    float* __restrict__ out)
{
    __shared__ float sacc[HH];
    __shared__ float sval[128];
    int r = blockIdx.x;
    int t = threadIdx.x;
    sacc[t]       = g_acc[(long)r * HH + t];
    sacc[t + 128] = g_acc[(long)r * HH + t + 128];
    __syncthreads();
    float dot = 0.f;
    if (t < CC) {
        dot = outb[t];
#pragma unroll 8
        for (int k = 0; k < HH; k++)
            dot = fmaf(sacc[k], outW[k * CC + t], dot);
    }
    sval[t] = (t < CC) ? dot : -1e30f;
    __syncthreads();
    for (int s = 64; s > 0; s >>= 1) {
        if (t < s) sval[t] = fmaxf(sval[t], sval[t + s]);
        __syncthreads();
    }
    float mx = sval[0];
    __syncthreads();
    sval[t] = (t < CC) ? expf(dot - mx) : 0.f;
    __syncthreads();
    for (int s = 64; s > 0; s >>= 1) {
        if (t < s) sval[t] += sval[t + s];
        __syncthreads();
    }
    float lse = logf(sval[0]) + mx;
    if (t < CC) out[(long)r * CC + t] = dot - lse;
}

// ---------------- launch ------------------------------------------------------
extern "C" void kernel_launch(void* const* d_in, const int* in_sizes, int n_in,
                              void* d_out, int out_size) {
    const float* x     = (const float*)d_in[0];
    const int*   e1    = (const int*)d_in[1];
    const int*   e2    = (const int*)d_in[2];
    const float* inW   = (const float*)d_in[3];
    const float* inb   = (const float*)d_in[4];
    const float* convW = (const float*)d_in[5];
    const float* convB = (const float*)d_in[6];
    const float* gamma = (const float*)d_in[7];
    const float* beta  = (const float*)d_in[8];
    const float* outW  = (const float*)d_in[9];
    const float* outb  = (const float*)d_in[10];
    const float* lw    = (const float*)d_in[11];
    float* out = (float*)d_out;

    float *p_h, *p_t, *p_acc, *p_d1, *p_d2, *p_s1, *p_s2, *p_n1, *p_n2, *p_stats;
    cudaGetSymbolAddress((void**)&p_h, g_h);
    cudaGetSymbolAddress((void**)&p_t, g_t);
    cudaGetSymbolAddress((void**)&p_acc, g_acc);
    cudaGetSymbolAddress((void**)&p_d1, g_dinv1);
    cudaGetSymbolAddress((void**)&p_d2, g_dinv2);
    cudaGetSymbolAddress((void**)&p_s1, g_self1);
    cudaGetSymbolAddress((void**)&p_s2, g_self2);
    cudaGetSymbolAddress((void**)&p_n1, g_norm1);
    cudaGetSymbolAddress((void**)&p_n2, g_norm2);
    cudaGetSymbolAddress((void**)&p_stats, g_stats);

    const int Z = 256;
    // adjacency normalization (recomputed every call; cheap)
    zero_kernel<<<(NN / 4 + Z - 1) / Z, Z>>>((float4*)p_d1, NN / 4);
    zero_kernel<<<(NN / 4 + Z - 1) / Z, Z>>>((float4*)p_d2, NN / 4);
    deg_kernel<<<(EE + Z - 1) / Z, Z>>>(e1, e2);
    dinv_kernel<<<(NN + Z - 1) / Z, Z>>>();
    norm_kernel<<<(EE + Z - 1) / Z, Z>>>(e1, e2);
    softmax_w_kernel<<<1, 32>>>(lw);

    const int NH4 = NN * HH / 4;                  // 3.2M float4
    zero_kernel<<<(NH4 + Z - 1) / Z, Z>>>((float4*)p_acc, NH4);

    // input FC: h = x @ in_W + in_b
    dim3 gemmGrid(HH / 128, (NN + 127) / 128);
    sgemm_bias_kernel<<<gemmGrid, 256>>>(x, inW, inb, p_h, NN, HH, FIN);

    for (int i = 0; i < LL; i++) {
        // t = h @ convW[i] + convB[i]
        sgemm_bias_kernel<<<gemmGrid, 256>>>(p_h, convW + (long)i * HH * HH,
                                             convB + (long)i * HH, p_t, NN, HH, HH);
        // h = scatter-add SpMM
        zero_kernel<<<(NH4 + Z - 1) / Z, Z>>>((float4*)p_h, NH4);
        zero_kernel<<<1, 128>>>((float4*)p_stats, 128);
        const int* ee = (i < LL / 2) ? e1 : e2;
        const float* nn = (i < LL / 2) ? p_n1 : p_n2;
        const float* ss = (i < LL / 2) ? p_s1 : p_s2;
        scatter_kernel<<<(EE + 7) / 8, 256>>>(p_t, ee, nn);
        self_add_kernel<<<(NH4 + Z - 1) / Z, Z>>>(p_t, ss);
        // BatchNorm + ReLU + weighted residual
        stats_kernel<<<(NN + 255) / 256, 256>>>();
        bn_finalize_kernel<<<1, 256>>>(gamma, beta, i);
        bn_relu_acc_kernel<<<(NH4 + Z - 1) / Z, Z>>>(i);
    }

    // out FC + log_softmax
    out_kernel<<<NN, 128>>>(outW, outb, out);
}

// round 6
// speedup vs baseline: 1.3769x; 1.3769x over previous
#include <cuda_runtime.h>
#include <math.h>

#define NN 50000
#define EE 800000
#define FIN 128
#define HH 256
#define CC 112
#define LL 8
#define EPSBN 1e-5f
#define NB_SCAN 196   // ceil(NN/256)

// ---------------- scratch (device globals; no allocation allowed) ------------
__device__ __align__(16) float g_h[NN * HH];
__device__ __align__(16) float g_t[NN * HH];
__device__ __align__(16) float g_acc[NN * HH];
__device__ __align__(16) int   g_deg1[NN];
__device__ __align__(16) int   g_deg2[NN];
__device__ __align__(16) int   g_row1[NN + 4];
__device__ __align__(16) int   g_row2[NN + 4];
__device__ __align__(16) int   g_cur1[NN];
__device__ __align__(16) int   g_cur2[NN];
__device__ __align__(16) int   g_src1[EE];
__device__ __align__(16) int   g_src2[EE];
__device__ __align__(16) float g_nrm1[EE];
__device__ __align__(16) float g_nrm2[EE];
__device__ __align__(16) float g_dinv1[NN];
__device__ __align__(16) float g_dinv2[NN];
__device__ __align__(16) float g_self1[NN];
__device__ __align__(16) float g_self2[NN];
__device__ __align__(16) int   g_part[256];
__device__ __align__(16) float g_stats[2 * HH];   // sum, sumsq
__device__ __align__(16) float g_ab[2 * HH];      // scale a, shift b
__device__ __align__(16) float g_w[LL];

// ---------------- utility kernels -------------------------------------------
__global__ void zero_kernel(float4* p, int n4) {
    int i = blockIdx.x * blockDim.x + threadIdx.x;
    if (i < n4) p[i] = make_float4(0.f, 0.f, 0.f, 0.f);
}

__global__ void deg_kernel(const int* __restrict__ e1, const int* __restrict__ e2) {
    int i = blockIdx.x * blockDim.x + threadIdx.x;
    if (i < EE) {
        atomicAdd(&g_deg1[e1[EE + i]], 1);
        atomicAdd(&g_deg2[e2[EE + i]], 1);
    }
}

__global__ void dinv_kernel() {
    int i = blockIdx.x * blockDim.x + threadIdx.x;
    if (i < NN) {
        float d1 = rsqrtf((float)g_deg1[i] + 1.0f);   // +1 = self loop
        float d2 = rsqrtf((float)g_deg2[i] + 1.0f);
        g_dinv1[i] = d1;
        g_dinv2[i] = d2;
        g_self1[i] = d1 * d1;
        g_self2[i] = d2 * d2;
    }
}

// block-local exclusive scan; writes block total to partial
__global__ void scan1_kernel(const int* __restrict__ deg, int* __restrict__ row,
                             int* __restrict__ partial) {
    __shared__ int s[256];
    int tid = threadIdx.x;
    int i = blockIdx.x * 256 + tid;
    int v = (i < NN) ? deg[i] : 0;
    s[tid] = v;
    __syncthreads();
#pragma unroll
    for (int off = 1; off < 256; off <<= 1) {
        int t = (tid >= off) ? s[tid - off] : 0;
        __syncthreads();
        s[tid] += t;
        __syncthreads();
    }
    if (i < NN) row[i] = s[tid] - v;   // exclusive
    if (tid == 255) partial[blockIdx.x] = s[255];
}

// exclusive scan of partials (single block)
__global__ void scan2_kernel(int* __restrict__ partial) {
    __shared__ int s[256];
    int tid = threadIdx.x;
    int v = (tid < NB_SCAN) ? partial[tid] : 0;
    s[tid] = v;
    __syncthreads();
#pragma unroll
    for (int off = 1; off < 256; off <<= 1) {
        int t = (tid >= off) ? s[tid - off] : 0;
        __syncthreads();
        s[tid] += t;
        __syncthreads();
    }
    if (tid < NB_SCAN) partial[tid] = s[tid] - v;
}

__global__ void scan3_kernel(int* __restrict__ row, const int* __restrict__ partial,
                             int* __restrict__ cur) {
    int i = blockIdx.x * blockDim.x + threadIdx.x;
    if (i < NN) {
        int r = row[i] + partial[i >> 8];
        row[i] = r;
        cur[i] = r;
    }
    if (i == 0) row[NN] = EE;
}

__global__ void fill_kernel(const int* __restrict__ e1, const int* __restrict__ e2) {
    int i = blockIdx.x * blockDim.x + threadIdx.x;
    if (i < EE) {
        int s1 = e1[i], c1 = e1[EE + i];
        int p = atomicAdd(&g_cur1[c1], 1);
        g_src1[p] = s1;
        g_nrm1[p] = g_dinv1[s1] * g_dinv1[c1];
        int s2 = e2[i], c2 = e2[EE + i];
        p = atomicAdd(&g_cur2[c2], 1);
        g_src2[p] = s2;
        g_nrm2[p] = g_dinv2[s2] * g_dinv2[c2];
    }
}

__global__ void softmax_w_kernel(const float* __restrict__ lw) {
    if (threadIdx.x == 0 && blockIdx.x == 0) {
        float m = lw[0];
        for (int i = 1; i < LL; i++) m = fmaxf(m, lw[i]);
        float e[LL];
        float s = 0.f;
        for (int i = 0; i < LL; i++) { e[i] = expf(lw[i] - m); s += e[i]; }
        float inv = 1.0f / s;
        for (int i = 0; i < LL; i++) g_w[i] = e[i] * inv;
    }
}

// ---------------- SGEMM: C = act(A) @ B + bias ------------------------------
// act(v, k) = relu(ab[k]*v + ab[HH+k]) when ab != nullptr (fused BN+ReLU).
// 128x128 tile, BK=16, 256 threads, 8x8 per thread.
__global__ __launch_bounds__(256) void sgemm_bias_kernel(
    const float* __restrict__ A, const float* __restrict__ B,
    const float* __restrict__ bias, float* __restrict__ C,
    int M, int Ncols, int K, const float* __restrict__ ab)
{
    __shared__ float As[16][128];
    __shared__ float Bs[16][128];
    const int tid = threadIdx.x;
    const int tx = tid & 15;
    const int ty = tid >> 4;
    const int rowBase = blockIdx.y * 128;
    const int colBase = blockIdx.x * 128;
    const int aRow = tid >> 2;          // 0..63
    const int aCol = (tid & 3) * 4;     // 0,4,8,12
    const int bRow = tid >> 5;          // 0..7
    const int bCol = (tid & 31) * 4;    // 0..124

    float acc[8][8];
#pragma unroll
    for (int i = 0; i < 8; i++)
#pragma unroll
        for (int j = 0; j < 8; j++) acc[i][j] = 0.f;

    for (int k0 = 0; k0 < K; k0 += 16) {
        float4 av = make_float4(1.f, 1.f, 1.f, 1.f);
        float4 bv0 = make_float4(0.f, 0.f, 0.f, 0.f);
        bool doAct = (ab != nullptr);
        if (doAct) {
            av = *(const float4*)(ab + k0 + aCol);
            bv0 = *(const float4*)(ab + HH + k0 + aCol);
        }
#pragma unroll
        for (int s = 0; s < 2; s++) {
            int r = aRow + s * 64;
            int gr = rowBase + r;
            float4 v = make_float4(0.f, 0.f, 0.f, 0.f);
            if (gr < M) {
                v = *(const float4*)(A + (long)gr * K + k0 + aCol);
                if (doAct) {
                    v.x = fmaxf(fmaf(v.x, av.x, bv0.x), 0.f);
                    v.y = fmaxf(fmaf(v.y, av.y, bv0.y), 0.f);
                    v.z = fmaxf(fmaf(v.z, av.z, bv0.z), 0.f);
                    v.w = fmaxf(fmaf(v.w, av.w, bv0.w), 0.f);
                }
            }
            As[aCol + 0][r] = v.x;
            As[aCol + 1][r] = v.y;
            As[aCol + 2][r] = v.z;
            As[aCol + 3][r] = v.w;
        }
#pragma unroll
        for (int s = 0; s < 2; s++) {
            int r = bRow + s * 8;
            int gc = colBase + bCol;
            float4 v = make_float4(0.f, 0.f, 0.f, 0.f);
            if (gc + 3 < Ncols) {
                v = *(const float4*)(B + (long)(k0 + r) * Ncols + gc);
            }
            *(float4*)(&Bs[r][bCol]) = v;
        }
        __syncthreads();
#pragma unroll
        for (int kk = 0; kk < 16; kk++) {
            float ar[8], br[8];
#pragma unroll
            for (int i = 0; i < 8; i++) ar[i] = As[kk][ty * 8 + i];
#pragma unroll
            for (int j = 0; j < 8; j++) br[j] = Bs[kk][tx * 8 + j];
#pragma unroll
            for (int i = 0; i < 8; i++)
#pragma unroll
                for (int j = 0; j < 8; j++)
                    acc[i][j] = fmaf(ar[i], br[j], acc[i][j]);
        }
        __syncthreads();
    }

#pragma unroll
    for (int i = 0; i < 8; i++) {
        int gr = rowBase + ty * 8 + i;
        if (gr >= M) continue;
#pragma unroll
        for (int j = 0; j < 8; j += 4) {
            int gc = colBase + tx * 8 + j;
            if (gc + 3 < Ncols) {
                float4 bv = *(const float4*)(bias + gc);
                float4 o;
                o.x = acc[i][j + 0] + bv.x;
                o.y = acc[i][j + 1] + bv.y;
                o.z = acc[i][j + 2] + bv.z;
                o.w = acc[i][j + 3] + bv.w;
                *(float4*)(C + (long)gr * Ncols + gc) = o;
            }
        }
    }
}

// ---------------- gather SpMM (CSR, warp per node, no atomics) ---------------
__global__ __launch_bounds__(256) void spmm_kernel(
    const float* __restrict__ t, const int* __restrict__ row,
    const int* __restrict__ src, const float* __restrict__ nrm,
    const float* __restrict__ selfn)
{
    int node = blockIdx.x * 8 + (threadIdx.x >> 5);
    if (node >= NN) return;
    int lane = threadIdx.x & 31;
    int beg = row[node];
    int end = row[node + 1];
    float4 a0 = make_float4(0.f, 0.f, 0.f, 0.f);
    float4 a1 = make_float4(0.f, 0.f, 0.f, 0.f);
    int e = beg;
    for (; e + 1 < end; e += 2) {
        int s0 = src[e], s1 = src[e + 1];
        float n0 = nrm[e], n1 = nrm[e + 1];
        const float4* p0 = (const float4*)(t + (long)s0 * HH);
        const float4* p1 = (const float4*)(t + (long)s1 * HH);
        float4 v00 = p0[lane], v01 = p0[lane + 32];
        float4 v10 = p1[lane], v11 = p1[lane + 32];
        a0.x = fmaf(v00.x, n0, a0.x); a0.y = fmaf(v00.y, n0, a0.y);
        a0.z = fmaf(v00.z, n0, a0.z); a0.w = fmaf(v00.w, n0, a0.w);
        a1.x = fmaf(v01.x, n0, a1.x); a1.y = fmaf(v01.y, n0, a1.y);
        a1.z = fmaf(v01.z, n0, a1.z); a1.w = fmaf(v01.w, n0, a1.w);
        a0.x = fmaf(v10.x, n1, a0.x); a0.y = fmaf(v10.y, n1, a0.y);
        a0.z = fmaf(v10.z, n1, a0.z); a0.w = fmaf(v10.w, n1, a0.w);
        a1.x = fmaf(v11.x, n1, a1.x); a1.y = fmaf(v11.y, n1, a1.y);
        a1.z = fmaf(v11.z, n1, a1.z); a1.w = fmaf(v11.w, n1, a1.w);
    }
    if (e < end) {
        int s0 = src[e];
        float n0 = nrm[e];
        const float4* p0 = (const float4*)(t + (long)s0 * HH);
        float4 v00 = p0[lane], v01 = p0[lane + 32];
        a0.x = fmaf(v00.x, n0, a0.x); a0.y = fmaf(v00.y, n0, a0.y);
        a0.z = fmaf(v00.z, n0, a0.z); a0.w = fmaf(v00.w, n0, a0.w);
        a1.x = fmaf(v01.x, n0, a1.x); a1.y = fmaf(v01.y, n0, a1.y);
        a1.z = fmaf(v01.z, n0, a1.z); a1.w = fmaf(v01.w, n0, a1.w);
    }
    // self loop
    float sf = selfn[node];
    const float4* sp = (const float4*)(t + (long)node * HH);
    float4 v0 = sp[lane], v1 = sp[lane + 32];
    a0.x = fmaf(v0.x, sf, a0.x); a0.y = fmaf(v0.y, sf, a0.y);
    a0.z = fmaf(v0.z, sf, a0.z); a0.w = fmaf(v0.w, sf, a0.w);
    a1.x = fmaf(v1.x, sf, a1.x); a1.y = fmaf(v1.y, sf, a1.y);
    a1.z = fmaf(v1.z, sf, a1.z); a1.w = fmaf(v1.w, sf, a1.w);

    float4* dst = (float4*)(g_h + (long)node * HH);
    dst[lane] = a0;
    dst[lane + 32] = a1;
}

// per-feature sum / sumsq partials
__global__ void stats_kernel() {
    int f = threadIdx.x;                 // 256 features
    int r0 = blockIdx.x * 256;
    int rend = min(r0 + 256, NN);
    float s = 0.f, q = 0.f;
    for (int r = r0; r < rend; r++) {
        float v = g_h[(long)r * HH + f];
        s += v;
        q = fmaf(v, v, q);
    }
    atomicAdd(&g_stats[f], s);
    atomicAdd(&g_stats[HH + f], q);
}

__global__ void bn_finalize_kernel(const float* __restrict__ gamma,
                                   const float* __restrict__ beta, int layer) {
    int f = threadIdx.x;
    float mu = g_stats[f] * (1.0f / NN);
    float var = g_stats[HH + f] * (1.0f / NN) - mu * mu;
    float rs = rsqrtf(var + EPSBN);
    float a = rs * gamma[layer * HH + f];
    float b = beta[layer * HH + f] - mu * a;
    g_ab[f] = a;
    g_ab[HH + f] = b;
}

// acc += w * relu(a*h + b)   (h stays raw; next GEMM applies same affine)
__global__ void acc_kernel(int layer) {
    int idx = blockIdx.x * blockDim.x + threadIdx.x;   // float4 index
    if (idx < NN * (HH / 4)) {
        int f4 = (idx & 63) * 4;
        float4 a = *(const float4*)(g_ab + f4);
        float4 b = *(const float4*)(g_ab + HH + f4);
        float4 v = ((const float4*)g_h)[idx];
        v.x = fmaxf(fmaf(v.x, a.x, b.x), 0.f);
        v.y = fmaxf(fmaf(v.y, a.y, b.y), 0.f);
        v.z = fmaxf(fmaf(v.z, a.z, b.z), 0.f);
        v.w = fmaxf(fmaf(v.w, a.w, b.w), 0.f);
        float w = g_w[layer];
        float4 ac = ((float4*)g_acc)[idx];
        ac.x = fmaf(w, v.x, ac.x);
        ac.y = fmaf(w, v.y, ac.y);
        ac.z = fmaf(w, v.z, ac.z);
        ac.w = fmaf(w, v.w, ac.w);
        ((float4*)g_acc)[idx] = ac;
    }
}

// fused out FC + log-softmax: one block per node row
__global__ __launch_bounds__(128) void out_kernel(
    const float* __restrict__ outW, const float* __restrict__ outb,
    float* __restrict__ out)
{
    __shared__ float sacc[HH];
    __shared__ float sval[128];
    int r = blockIdx.x;
    int t = threadIdx.x;
    sacc[t]       = g_acc[(long)r * HH + t];
    sacc[t + 128] = g_acc[(long)r * HH + t + 128];
    __syncthreads();
    float dot = 0.f;
    if (t < CC) {
        dot = outb[t];
#pragma unroll 8
        for (int k = 0; k < HH; k++)
            dot = fmaf(sacc[k], outW[k * CC + t], dot);
    }
    sval[t] = (t < CC) ? dot : -1e30f;
    __syncthreads();
    for (int s = 64; s > 0; s >>= 1) {
        if (t < s) sval[t] = fmaxf(sval[t], sval[t + s]);
        __syncthreads();
    }
    float mx = sval[0];
    __syncthreads();
    sval[t] = (t < CC) ? expf(dot - mx) : 0.f;
    __syncthreads();
    for (int s = 64; s > 0; s >>= 1) {
        if (t < s) sval[t] += sval[t + s];
        __syncthreads();
    }
    float lse = logf(sval[0]) + mx;
    if (t < CC) out[(long)r * CC + t] = dot - lse;
}

// ---------------- launch ------------------------------------------------------
extern "C" void kernel_launch(void* const* d_in, const int* in_sizes, int n_in,
                              void* d_out, int out_size) {
    const float* x     = (const float*)d_in[0];
    const int*   e1    = (const int*)d_in[1];
    const int*   e2    = (const int*)d_in[2];
    const float* inW   = (const float*)d_in[3];
    const float* inb   = (const float*)d_in[4];
    const float* convW = (const float*)d_in[5];
    const float* convB = (const float*)d_in[6];
    const float* gamma = (const float*)d_in[7];
    const float* beta  = (const float*)d_in[8];
    const float* outW  = (const float*)d_in[9];
    const float* outb  = (const float*)d_in[10];
    const float* lw    = (const float*)d_in[11];
    float* out = (float*)d_out;

    float *p_h, *p_t, *p_acc, *p_stats, *p_s1, *p_s2, *p_n1, *p_n2;
    int *p_deg1, *p_deg2, *p_row1, *p_row2, *p_cur1, *p_cur2, *p_src1, *p_src2, *p_part;
    cudaGetSymbolAddress((void**)&p_h, g_h);
    cudaGetSymbolAddress((void**)&p_t, g_t);
    cudaGetSymbolAddress((void**)&p_acc, g_acc);
    cudaGetSymbolAddress((void**)&p_stats, g_stats);
    cudaGetSymbolAddress((void**)&p_s1, g_self1);
    cudaGetSymbolAddress((void**)&p_s2, g_self2);
    cudaGetSymbolAddress((void**)&p_n1, g_nrm1);
    cudaGetSymbolAddress((void**)&p_n2, g_nrm2);
    cudaGetSymbolAddress((void**)&p_deg1, g_deg1);
    cudaGetSymbolAddress((void**)&p_deg2, g_deg2);
    cudaGetSymbolAddress((void**)&p_row1, g_row1);
    cudaGetSymbolAddress((void**)&p_row2, g_row2);
    cudaGetSymbolAddress((void**)&p_cur1, g_cur1);
    cudaGetSymbolAddress((void**)&p_cur2, g_cur2);
    cudaGetSymbolAddress((void**)&p_src1, g_src1);
    cudaGetSymbolAddress((void**)&p_src2, g_src2);
    cudaGetSymbolAddress((void**)&p_part, g_part);

    const int Z = 256;
    // ---- adjacency prep: degrees, dinv, CSR build ----
    zero_kernel<<<(NN / 4 + Z - 1) / Z, Z>>>((float4*)p_deg1, NN / 4);
    zero_kernel<<<(NN / 4 + Z - 1) / Z, Z>>>((float4*)p_deg2, NN / 4);
    deg_kernel<<<(EE + Z - 1) / Z, Z>>>(e1, e2);
    dinv_kernel<<<(NN + Z - 1) / Z, Z>>>();
    scan1_kernel<<<NB_SCAN, 256>>>(p_deg1, p_row1, p_part);
    scan2_kernel<<<1, 256>>>(p_part);
    scan3_kernel<<<(NN + Z - 1) / Z, Z>>>(p_row1, p_part, p_cur1);
    scan1_kernel<<<NB_SCAN, 256>>>(p_deg2, p_row2, p_part);
    scan2_kernel<<<1, 256>>>(p_part);
    scan3_kernel<<<(NN + Z - 1) / Z, Z>>>(p_row2, p_part, p_cur2);
    fill_kernel<<<(EE + Z - 1) / Z, Z>>>(e1, e2);
    softmax_w_kernel<<<1, 32>>>(lw);

    const int NH4 = NN * HH / 4;
    zero_kernel<<<(NH4 + Z - 1) / Z, Z>>>((float4*)p_acc, NH4);

    // input FC: h = x @ in_W + in_b (no activation)
    dim3 gemmGrid(HH / 128, (NN + 127) / 128);
    sgemm_bias_kernel<<<gemmGrid, 256>>>(x, inW, inb, p_h, NN, HH, FIN, nullptr);

    for (int i = 0; i < LL; i++) {
        // t = act(h) @ convW[i] + convB[i]; act = identity for i==0, else BN+ReLU of layer i-1
        const float* abp = nullptr;
        if (i > 0) {
            float* tmp;
            cudaGetSymbolAddress((void**)&tmp, g_ab);
            abp = tmp;
        }
        sgemm_bias_kernel<<<gemmGrid, 256>>>(p_h, convW + (long)i * HH * HH,
                                             convB + (long)i * HH, p_t, NN, HH, HH, abp);
        // h = A_hat_norm @ t via CSR gather (includes self loop)
        const int* rowp = (i < LL / 2) ? p_row1 : p_row2;
        const int* srcp = (i < LL / 2) ? p_src1 : p_src2;
        const float* nrmp = (i < LL / 2) ? p_n1 : p_n2;
        const float* selfp = (i < LL / 2) ? p_s1 : p_s2;
        spmm_kernel<<<(NN + 7) / 8, 256>>>(p_t, rowp, srcp, nrmp, selfp);
        // BN stats + coefficients
        zero_kernel<<<1, 128>>>((float4*)p_stats, 128);
        stats_kernel<<<(NN + 255) / 256, 256>>>();
        bn_finalize_kernel<<<1, 256>>>(gamma, beta, i);
        // weighted residual: acc += w[i] * relu(a*h + b)
        acc_kernel<<<(NH4 + Z - 1) / Z, Z>>>(i);
    }

    // out FC + log_softmax
    out_kernel<<<NN, 128>>>(outW, outb, out);
}

// round 8
// speedup vs baseline: 1.4250x; 1.0349x over previous
#include <cuda_runtime.h>
#include <math.h>

#define NN 50000
#define EE 800000
#define FIN 128
#define HH 256
#define CC 112
#define LL 8
#define EPSBN 1e-5f
#define NB_SCAN 196   // ceil(NN/256)

typedef unsigned long long u64;

__device__ __forceinline__ u64 pack2(float lo, float hi) {
    u64 d; asm("mov.b64 %0, {%1, %2};" : "=l"(d) : "f"(lo), "f"(hi)); return d;
}
__device__ __forceinline__ void fma2(u64& d, u64 a, u64 b, u64 c) {
    asm("fma.rn.f32x2 %0, %1, %2, %3;" : "=l"(d) : "l"(a), "l"(b), "l"(c));
}
__device__ __forceinline__ float2 unpack2(u64 v) {
    float2 r; asm("mov.b64 {%0, %1}, %2;" : "=f"(r.x), "=f"(r.y) : "l"(v)); return r;
}

// ---------------- scratch (device globals; no allocation allowed) ------------
__device__ __align__(16) float g_h[NN * HH];
__device__ __align__(16) float g_t[NN * HH];
__device__ __align__(16) float g_acc[NN * HH];
__device__ __align__(16) int   g_deg1[NN];
__device__ __align__(16) int   g_deg2[NN];
__device__ __align__(16) int   g_row1[NN + 4];
__device__ __align__(16) int   g_row2[NN + 4];
__device__ __align__(16) int   g_cur1[NN];
__device__ __align__(16) int   g_cur2[NN];
__device__ __align__(16) int   g_src1[EE];
__device__ __align__(16) int   g_src2[EE];
__device__ __align__(16) float g_nrm1[EE];
__device__ __align__(16) float g_nrm2[EE];
__device__ __align__(16) float g_dinv1[NN];
__device__ __align__(16) float g_dinv2[NN];
__device__ __align__(16) float g_self1[NN];
__device__ __align__(16) float g_self2[NN];
__device__ __align__(16) int   g_part[256];
__device__ __align__(16) float g_stats[2 * HH];   // sum, sumsq
__device__ __align__(16) float g_ab[2 * HH];      // scale a, shift b
__device__ __align__(16) float g_w[LL];

// ---------------- utility kernels -------------------------------------------
__global__ void zero_kernel(float4* p, int n4) {
    int i = blockIdx.x * blockDim.x + threadIdx.x;
    if (i < n4) p[i] = make_float4(0.f, 0.f, 0.f, 0.f);
}

__global__ void deg_kernel(const int* __restrict__ e1, const int* __restrict__ e2) {
    int i = blockIdx.x * blockDim.x + threadIdx.x;
    if (i < EE) {
        atomicAdd(&g_deg1[e1[EE + i]], 1);
        atomicAdd(&g_deg2[e2[EE + i]], 1);
    }
}

__global__ void dinv_kernel() {
    int i = blockIdx.x * blockDim.x + threadIdx.x;
    if (i < NN) {
        float d1 = rsqrtf((float)g_deg1[i] + 1.0f);   // +1 = self loop
        float d2 = rsqrtf((float)g_deg2[i] + 1.0f);
        g_dinv1[i] = d1;
        g_dinv2[i] = d2;
        g_self1[i] = d1 * d1;
        g_self2[i] = d2 * d2;
    }
}

// block-local exclusive scan; writes block total to partial
__global__ void scan1_kernel(const int* __restrict__ deg, int* __restrict__ row,
                             int* __restrict__ partial) {
    __shared__ int s[256];
    int tid = threadIdx.x;
    int i = blockIdx.x * 256 + tid;
    int v = (i < NN) ? deg[i] : 0;
    s[tid] = v;
    __syncthreads();
#pragma unroll
    for (int off = 1; off < 256; off <<= 1) {
        int t = (tid >= off) ? s[tid - off] : 0;
        __syncthreads();
        s[tid] += t;
        __syncthreads();
    }
    if (i < NN) row[i] = s[tid] - v;   // exclusive
    if (tid == 255) partial[blockIdx.x] = s[255];
}

__global__ void scan2_kernel(int* __restrict__ partial) {
    __shared__ int s[256];
    int tid = threadIdx.x;
    int v = (tid < NB_SCAN) ? partial[tid] : 0;
    s[tid] = v;
    __syncthreads();
#pragma unroll
    for (int off = 1; off < 256; off <<= 1) {
        int t = (tid >= off) ? s[tid - off] : 0;
        __syncthreads();
        s[tid] += t;
        __syncthreads();
    }
    if (tid < NB_SCAN) partial[tid] = s[tid] - v;
}

__global__ void scan3_kernel(int* __restrict__ row, const int* __restrict__ partial,
                             int* __restrict__ cur) {
    int i = blockIdx.x * blockDim.x + threadIdx.x;
    if (i < NN) {
        int r = row[i] + partial[i >> 8];
        row[i] = r;
        cur[i] = r;
    }
    if (i == 0) row[NN] = EE;
}

__global__ void fill_kernel(const int* __restrict__ e1, const int* __restrict__ e2) {
    int i = blockIdx.x * blockDim.x + threadIdx.x;
    if (i < EE) {
        int s1 = e1[i], c1 = e1[EE + i];
        int p = atomicAdd(&g_cur1[c1], 1);
        g_src1[p] = s1;
        g_nrm1[p] = g_dinv1[s1] * g_dinv1[c1];
        int s2 = e2[i], c2 = e2[EE + i];
        p = atomicAdd(&g_cur2[c2], 1);
        g_src2[p] = s2;
        g_nrm2[p] = g_dinv2[s2] * g_dinv2[c2];
    }
}

__global__ void softmax_w_kernel(const float* __restrict__ lw) {
    if (threadIdx.x == 0 && blockIdx.x == 0) {
        float m = lw[0];
        for (int i = 1; i < LL; i++) m = fmaxf(m, lw[i]);
        float e[LL];
        float s = 0.f;
        for (int i = 0; i < LL; i++) { e[i] = expf(lw[i] - m); s += e[i]; }
        float inv = 1.0f / s;
        for (int i = 0; i < LL; i++) g_w[i] = e[i] * inv;
    }
}

// ---------------- SGEMM: C = act(A) @ B + bias, packed f32x2 FMA -------------
// act(v,k) = relu(ab[k]*v + ab[HH+k]) when ab != nullptr (fused BN+ReLU).
// When wPtr != nullptr and blockIdx.x == 0, also: accOut[r,k] += wPtr[widx]*act(A[r,k]).
// 128x128 tile, BK=16, 256 threads, 8x8 per thread (stored as 8x4 f32x2 pairs).
__global__ __launch_bounds__(256) void sgemm_bias_kernel(
    const float* __restrict__ A, const float* __restrict__ B,
    const float* __restrict__ bias, float* __restrict__ C,
    int M, int Ncols, int K, const float* __restrict__ ab,
    const float* __restrict__ wPtr, int widx, float* __restrict__ accOut)
{
    __shared__ float As[16][128];
    __shared__ float Bs[16][128];
    const int tid = threadIdx.x;
    const int tx = tid & 15;
    const int ty = tid >> 4;
    const int rowBase = blockIdx.y * 128;
    const int colBase = blockIdx.x * 128;
    const int aRow = tid >> 2;          // 0..63
    const int aCol = (tid & 3) * 4;     // 0,4,8,12
    const int bRow = tid >> 5;          // 0..7
    const int bCol = (tid & 31) * 4;    // 0..124

    const bool doAct = (ab != nullptr);
    const bool doAcc = (wPtr != nullptr) && (blockIdx.x == 0);
    const float wres = doAcc ? wPtr[widx] : 0.f;

    u64 acc2[8][4];
#pragma unroll
    for (int i = 0; i < 8; i++)
#pragma unroll
        for (int j = 0; j < 4; j++) acc2[i][j] = 0ull;

    for (int k0 = 0; k0 < K; k0 += 16) {
        float4 av = make_float4(1.f, 1.f, 1.f, 1.f);
        float4 bv0 = make_float4(0.f, 0.f, 0.f, 0.f);
        if (doAct) {
            av = *(const float4*)(ab + k0 + aCol);
            bv0 = *(const float4*)(ab + HH + k0 + aCol);
        }
#pragma unroll
        for (int s = 0; s < 2; s++) {
            int r = aRow + s * 64;
            int gr = rowBase + r;
            float4 v = make_float4(0.f, 0.f, 0.f, 0.f);
            if (gr < M) {
                v = *(const float4*)(A + (long)gr * K + k0 + aCol);
                if (doAct) {
                    v.x = fmaxf(fmaf(v.x, av.x, bv0.x), 0.f);
                    v.y = fmaxf(fmaf(v.y, av.y, bv0.y), 0.f);
                    v.z = fmaxf(fmaf(v.z, av.z, bv0.z), 0.f);
                    v.w = fmaxf(fmaf(v.w, av.w, bv0.w), 0.f);
                }
                if (doAcc) {
                    float* ap = accOut + (long)gr * K + k0 + aCol;
                    float4 ac = *(const float4*)ap;
                    ac.x = fmaf(wres, v.x, ac.x);
                    ac.y = fmaf(wres, v.y, ac.y);
                    ac.z = fmaf(wres, v.z, ac.z);
                    ac.w = fmaf(wres, v.w, ac.w);
                    *(float4*)ap = ac;
                }
            }
            As[aCol + 0][r] = v.x;
            As[aCol + 1][r] = v.y;
            As[aCol + 2][r] = v.z;
            As[aCol + 3][r] = v.w;
        }
#pragma unroll
        for (int s = 0; s < 2; s++) {
            int r = bRow + s * 8;
            int gc = colBase + bCol;
            float4 v = make_float4(0.f, 0.f, 0.f, 0.f);
            if (gc + 3 < Ncols) {
                v = *(const float4*)(B + (long)(k0 + r) * Ncols + gc);
            }
            *(float4*)(&Bs[r][bCol]) = v;
        }
        __syncthreads();
#pragma unroll
        for (int kk = 0; kk < 16; kk++) {
            const float* arow = &As[kk][ty * 8];
            const float* brow = &Bs[kk][tx * 8];
            u64 bq[4];
            u64 ad[8];
#pragma unroll
            for (int p = 0; p < 4; p++) {
                float2 af = *(const float2*)(arow + 2 * p);
                ad[2 * p]     = pack2(af.x, af.x);
                ad[2 * p + 1] = pack2(af.y, af.y);
                bq[p] = *(const u64*)(brow + 2 * p);
            }
#pragma unroll
            for (int i = 0; i < 8; i++)
#pragma unroll
                for (int jp = 0; jp < 4; jp++)
                    fma2(acc2[i][jp], ad[i], bq[jp], acc2[i][jp]);
        }
        __syncthreads();
    }

#pragma unroll
    for (int i = 0; i < 8; i++) {
        int gr = rowBase + ty * 8 + i;
        if (gr >= M) continue;
#pragma unroll
        for (int j = 0; j < 2; j++) {
            int gc = colBase + tx * 8 + j * 4;
            if (gc + 3 < Ncols) {
                float4 bv = *(const float4*)(bias + gc);
                float2 p0 = unpack2(acc2[i][j * 2]);
                float2 p1 = unpack2(acc2[i][j * 2 + 1]);
                float4 o;
                o.x = p0.x + bv.x;
                o.y = p0.y + bv.y;
                o.z = p1.x + bv.z;
                o.w = p1.y + bv.w;
                *(float4*)(C + (long)gr * Ncols + gc) = o;
            }
        }
    }
}

// ---------------- gather SpMM (CSR, warp per node, no atomics) ---------------
__global__ __launch_bounds__(256) void spmm_kernel(
    const float* __restrict__ t, const int* __restrict__ row,
    const int* __restrict__ src, const float* __restrict__ nrm,
    const float* __restrict__ selfn)
{
    int node = blockIdx.x * 8 + (threadIdx.x >> 5);
    if (node >= NN) return;
    int lane = threadIdx.x & 31;
    int beg = row[node];
    int end = row[node + 1];
    float4 a0 = make_float4(0.f, 0.f, 0.f, 0.f);
    float4 a1 = make_float4(0.f, 0.f, 0.f, 0.f);
    int e = beg;
    for (; e + 1 < end; e += 2) {
        int s0 = src[e], s1 = src[e + 1];
        float n0 = nrm[e], n1 = nrm[e + 1];
        const float4* p0 = (const float4*)(t + (long)s0 * HH);
        const float4* p1 = (const float4*)(t + (long)s1 * HH);
        float4 v00 = p0[lane], v01 = p0[lane + 32];
        float4 v10 = p1[lane], v11 = p1[lane + 32];
        a0.x = fmaf(v00.x, n0, a0.x); a0.y = fmaf(v00.y, n0, a0.y);
        a0.z = fmaf(v00.z, n0, a0.z); a0.w = fmaf(v00.w, n0, a0.w);
        a1.x = fmaf(v01.x, n0, a1.x); a1.y = fmaf(v01.y, n0, a1.y);
        a1.z = fmaf(v01.z, n0, a1.z); a1.w = fmaf(v01.w, n0, a1.w);
        a0.x = fmaf(v10.x, n1, a0.x); a0.y = fmaf(v10.y, n1, a0.y);
        a0.z = fmaf(v10.z, n1, a0.z); a0.w = fmaf(v10.w, n1, a0.w);
        a1.x = fmaf(v11.x, n1, a1.x); a1.y = fmaf(v11.y, n1, a1.y);
        a1.z = fmaf(v11.z, n1, a1.z); a1.w = fmaf(v11.w, n1, a1.w);
    }
    if (e < end) {
        int s0 = src[e];
        float n0 = nrm[e];
        const float4* p0 = (const float4*)(t + (long)s0 * HH);
        float4 v00 = p0[lane], v01 = p0[lane + 32];
        a0.x = fmaf(v00.x, n0, a0.x); a0.y = fmaf(v00.y, n0, a0.y);
        a0.z = fmaf(v00.z, n0, a0.z); a0.w = fmaf(v00.w, n0, a0.w);
        a1.x = fmaf(v01.x, n0, a1.x); a1.y = fmaf(v01.y, n0, a1.y);
        a1.z = fmaf(v01.z, n0, a1.z); a1.w = fmaf(v01.w, n0, a1.w);
    }
    // self loop
    float sf = selfn[node];
    const float4* sp = (const float4*)(t + (long)node * HH);
    float4 v0 = sp[lane], v1 = sp[lane + 32];
    a0.x = fmaf(v0.x, sf, a0.x); a0.y = fmaf(v0.y, sf, a0.y);
    a0.z = fmaf(v0.z, sf, a0.z); a0.w = fmaf(v0.w, sf, a0.w);
    a1.x = fmaf(v1.x, sf, a1.x); a1.y = fmaf(v1.y, sf, a1.y);
    a1.z = fmaf(v1.z, sf, a1.z); a1.w = fmaf(v1.w, sf, a1.w);

    float4* dst = (float4*)(g_h + (long)node * HH);
    dst[lane] = a0;
    dst[lane + 32] = a1;
}

// per-feature sum / sumsq partials (128 rows per block)
__global__ void stats_kernel() {
    int f = threadIdx.x;                 // 256 features
    int r0 = blockIdx.x * 128;
    int rend = min(r0 + 128, NN);
    float s = 0.f, q = 0.f;
    for (int r = r0; r < rend; r++) {
        float v = g_h[(long)r * HH + f];
        s += v;
        q = fmaf(v, v, q);
    }
    atomicAdd(&g_stats[f], s);
    atomicAdd(&g_stats[HH + f], q);
}

__global__ void bn_finalize_kernel(const float* __restrict__ gamma,
                                   const float* __restrict__ beta, int layer) {
    int f = threadIdx.x;
    float mu = g_stats[f] * (1.0f / NN);
    float var = g_stats[HH + f] * (1.0f / NN) - mu * mu;
    float rs = rsqrtf(var + EPSBN);
    float a = rs * gamma[layer * HH + f];
    float b = beta[layer * HH + f] - mu * a;
    g_ab[f] = a;
    g_ab[HH + f] = b;
}

// fused (layer-7 residual) + out FC + log-softmax: one block per node row
__global__ __launch_bounds__(128) void out_kernel(
    const float* __restrict__ outW, const float* __restrict__ outb,
    float* __restrict__ out)
{
    __shared__ float sacc[HH];
    __shared__ float sval[128];
    int r = blockIdx.x;
    int t = threadIdx.x;
    float w7 = g_w[LL - 1];
#pragma unroll
    for (int s = 0; s < 2; s++) {
        int f = t + s * 128;
        float hv = g_h[(long)r * HH + f];
        float act = fmaxf(fmaf(hv, g_ab[f], g_ab[HH + f]), 0.f);
        sacc[f] = fmaf(w7, act, g_acc[(long)r * HH + f]);
    }
    __syncthreads();
    float dot = 0.f;
    if (t < CC) {
        dot = outb[t];
#pragma unroll 8
        for (int k = 0; k < HH; k++)
            dot = fmaf(sacc[k], outW[k * CC + t], dot);
    }
    sval[t] = (t < CC) ? dot : -1e30f;
    __syncthreads();
    for (int s = 64; s > 0; s >>= 1) {
        if (t < s) sval[t] = fmaxf(sval[t], sval[t + s]);
        __syncthreads();
    }
    float mx = sval[0];
    __syncthreads();
    sval[t] = (t < CC) ? expf(dot - mx) : 0.f;
    __syncthreads();
    for (int s = 64; s > 0; s >>= 1) {
        if (t < s) sval[t] += sval[t + s];
        __syncthreads();
    }
    float lse = logf(sval[0]) + mx;
    if (t < CC) out[(long)r * CC + t] = dot - lse;
}

// ---------------- launch ------------------------------------------------------
extern "C" void kernel_launch(void* const* d_in, const int* in_sizes, int n_in,
                              void* d_out, int out_size) {
    const float* x     = (const float*)d_in[0];
    const int*   e1    = (const int*)d_in[1];
    const int*   e2    = (const int*)d_in[2];
    const float* inW   = (const float*)d_in[3];
    const float* inb   = (const float*)d_in[4];
    const float* convW = (const float*)d_in[5];
    const float* convB = (const float*)d_in[6];
    const float* gamma = (const float*)d_in[7];
    const float* beta  = (const float*)d_in[8];
    const float* outW  = (const float*)d_in[9];
    const float* outb  = (const float*)d_in[10];
    const float* lw    = (const float*)d_in[11];
    float* out = (float*)d_out;

    float *p_h, *p_t, *p_acc, *p_stats, *p_s1, *p_s2, *p_n1, *p_n2, *p_ab, *p_w;
    int *p_deg1, *p_deg2, *p_row1, *p_row2, *p_cur1, *p_cur2, *p_src1, *p_src2, *p_part;
    cudaGetSymbolAddress((void**)&p_h, g_h);
    cudaGetSymbolAddress((void**)&p_t, g_t);
    cudaGetSymbolAddress((void**)&p_acc, g_acc);
    cudaGetSymbolAddress((void**)&p_stats, g_stats);
    cudaGetSymbolAddress((void**)&p_ab, g_ab);
    cudaGetSymbolAddress((void**)&p_w, g_w);
    cudaGetSymbolAddress((void**)&p_s1, g_self1);
    cudaGetSymbolAddress((void**)&p_s2, g_self2);
    cudaGetSymbolAddress((void**)&p_n1, g_nrm1);
    cudaGetSymbolAddress((void**)&p_n2, g_nrm2);
    cudaGetSymbolAddress((void**)&p_deg1, g_deg1);
    cudaGetSymbolAddress((void**)&p_deg2, g_deg2);
    cudaGetSymbolAddress((void**)&p_row1, g_row1);
    cudaGetSymbolAddress((void**)&p_row2, g_row2);
    cudaGetSymbolAddress((void**)&p_cur1, g_cur1);
    cudaGetSymbolAddress((void**)&p_cur2, g_cur2);
    cudaGetSymbolAddress((void**)&p_src1, g_src1);
    cudaGetSymbolAddress((void**)&p_src2, g_src2);
    cudaGetSymbolAddress((void**)&p_part, g_part);

    const int Z = 256;
    // ---- adjacency prep: degrees, dinv, CSR build ----
    zero_kernel<<<(NN / 4 + Z - 1) / Z, Z>>>((float4*)p_deg1, NN / 4);
    zero_kernel<<<(NN / 4 + Z - 1) / Z, Z>>>((float4*)p_deg2, NN / 4);
    deg_kernel<<<(EE + Z - 1) / Z, Z>>>(e1, e2);
    dinv_kernel<<<(NN + Z - 1) / Z, Z>>>();
    scan1_kernel<<<NB_SCAN, 256>>>(p_deg1, p_row1, p_part);
    scan2_kernel<<<1, 256>>>(p_part);
    scan3_kernel<<<(NN + Z - 1) / Z, Z>>>(p_row1, p_part, p_cur1);
    scan1_kernel<<<NB_SCAN, 256>>>(p_deg2, p_row2, p_part);
    scan2_kernel<<<1, 256>>>(p_part);
    scan3_kernel<<<(NN + Z - 1) / Z, Z>>>(p_row2, p_part, p_cur2);
    fill_kernel<<<(EE + Z - 1) / Z, Z>>>(e1, e2);
    softmax_w_kernel<<<1, 32>>>(lw);

    const int NH4 = NN * HH / 4;
    zero_kernel<<<(NH4 + Z - 1) / Z, Z>>>((float4*)p_acc, NH4);

    // input FC: h = x @ in_W + in_b (no activation, no residual)
    dim3 gemmGrid(HH / 128, (NN + 127) / 128);
    sgemm_bias_kernel<<<gemmGrid, 256>>>(x, inW, inb, p_h, NN, HH, FIN,
                                         nullptr, nullptr, 0, nullptr);

    for (int i = 0; i < LL; i++) {
        // t = act(h) @ convW[i] + convB[i]
        // act = identity for i==0, else BN+ReLU of layer i-1.
        // For i>0, block x==0 also accumulates acc += w[i-1]*act(h) during A load.
        const float* abp = (i > 0) ? p_ab : nullptr;
        const float* wp  = (i > 0) ? p_w : nullptr;
        sgemm_bias_kernel<<<gemmGrid, 256>>>(p_h, convW + (long)i * HH * HH,
                                             convB + (long)i * HH, p_t, NN, HH, HH,
                                             abp, wp, i - 1, p_acc);
        // h = A_hat_norm @ t via CSR gather (includes self loop)
        const int* rowp = (i < LL / 2) ? p_row1 : p_row2;
        const int* srcp = (i < LL / 2) ? p_src1 : p_src2;
        const float* nrmp = (i < LL / 2) ? p_n1 : p_n2;
        const float* selfp = (i < LL / 2) ? p_s1 : p_s2;
        spmm_kernel<<<(NN + 7) / 8, 256>>>(p_t, rowp, srcp, nrmp, selfp);
        // BN stats + coefficients
        zero_kernel<<<1, 128>>>((float4*)p_stats, 128);
        stats_kernel<<<(NN + 127) / 128, 256>>>();
        bn_finalize_kernel<<<1, 256>>>(gamma, beta, i);
    }

    // out FC (+ layer-7 weighted residual) + log_softmax
    out_kernel<<<NN, 128>>>(outW, outb, out);
}